// round 11
// baseline (speedup 1.0000x reference)
#include <cuda_runtime.h>
#include <stdint.h>

// CritiGraph: ct_val[t,s,c,p] = (sum_p' d - d[p] + d(cnc,pos)[c,p]) / TP
// d(a,b,norm) = sign(a)*sign(b) * (1 - e/16) * norm, e = frexp_exp(|a|^|b| + 1)
// No-LUT identity: r = cl*m + (fb - m), m = ±norm/128 (sign via bit31 XOR),
// cl = clz((xor+1)<<15).  Packed f32x2 FMA epilogue; 256-bit v4.b64 stores.
//
// R11: 128-thread blocks, 2 adjacent connections per thread (64B contiguous ->
// 2x STG.256/iter). 1024 half-size blocks -> ~13.8 blocks/SM -> better balance.

#define Tn 128
#define Sn 128
#define Cn 257
#define TPn 8
#define S_CHUNK 16
#define ROW_FLOATS (Cn * TPn)   // 2056 floats = 8224B
#define T_SPLIT 104

__device__ __forceinline__ uint32_t packsgn(int v) {
    uint32_t a = (uint32_t)(v < 0 ? -v : v);       // |v| <= 65535
    return a | ((uint32_t)v & 0x80000000u);        // sign lives in bit 31
}

__device__ __forceinline__ uint64_t pkf(float lo, float hi) {
    uint64_t r; asm("mov.b64 %0, {%1, %2};" : "=l"(r) : "f"(lo), "f"(hi)); return r;
}
__device__ __forceinline__ uint64_t pku(uint32_t lo, uint32_t hi) {
    uint64_t r; asm("mov.b64 %0, {%1, %2};" : "=l"(r) : "r"(lo), "r"(hi)); return r;
}
__device__ __forceinline__ uint64_t ffma2(uint64_t a, uint64_t b, uint64_t c) {
    uint64_t r; asm("fma.rn.f32x2 %0, %1, %2, %3;" : "=l"(r) : "l"(a), "l"(b), "l"(c)); return r;
}

#define NEG1X2 0xBF800000BF800000ULL   // packed (-1.0f, -1.0f)

__device__ __forceinline__ uint64_t pair2(uint32_t a0, uint32_t a1,
                                          uint32_t pw0, uint32_t pw1,
                                          uint32_t nsb, uint64_t fb2, uint64_t neg1) {
    const uint32_t t0 = a0 ^ pw0;
    const uint32_t t1 = a1 ^ pw1;
    const uint32_t m0 = nsb ^ (t0 & 0x80000000u);
    const uint32_t m1 = nsb ^ (t1 & 0x80000000u);
    const float f0 = (float)__clz(t0 * 32768u + 32768u);
    const float f1 = (float)__clz(t1 * 32768u + 32768u);
    const uint64_t m2  = pku(m0, m1);
    const uint64_t cl2 = pkf(f0, f1);
    return ffma2(cl2, m2, ffma2(m2, neg1, fb2));   // (cl-1)*m + fb
}

__device__ __forceinline__ void st4_el(float* p, uint64_t r0, uint64_t r1,
                                       uint64_t r2, uint64_t r3) {
    asm volatile("st.global.L2::evict_last.v4.b64 [%0], {%1,%2,%3,%4};"
                 :: "l"(p), "l"(r0), "l"(r1), "l"(r2), "l"(r3) : "memory");
}
__device__ __forceinline__ void st4_ef(float* p, uint64_t r0, uint64_t r1,
                                       uint64_t r2, uint64_t r3) {
    asm volatile("st.global.L2::evict_first.v4.b64 [%0], {%1,%2,%3,%4};"
                 :: "l"(p), "l"(r0), "l"(r1), "l"(r2), "l"(r3) : "memory");
}

template<bool EL>
__device__ __forceinline__ void hot_loop(
    const uint32_t (&a)[16], const uint32_t (*sm_apw)[TPn], const float (*sm_fb)[TPn],
    const uint32_t* sm_nsb, float* base)
{
    const uint64_t neg1 = NEG1X2;
    #pragma unroll
    for (int sl = 0; sl < S_CHUNK; sl++) {
        const uint4 apw0 = *(const uint4*)&sm_apw[sl][0];
        const uint4 apw1 = *(const uint4*)&sm_apw[sl][4];
        uint64_t fb01, fb23, fb45, fb67;
        {
            uint32_t sa = (uint32_t)__cvta_generic_to_shared(&sm_fb[sl][0]);
            asm("ld.shared.v2.u64 {%0,%1}, [%2];" : "=l"(fb01), "=l"(fb23) : "r"(sa));
            asm("ld.shared.v2.u64 {%0,%1}, [%2];" : "=l"(fb45), "=l"(fb67) : "r"(sa + 16));
        }
        const uint32_t nsb = sm_nsb[sl];

        // connection A = 2*tid  (a[0..7]),  connection B = 2*tid+1  (a[8..15])
        uint64_t rA0 = pair2(a[0],  a[1],  apw0.x, apw0.y, nsb, fb01, neg1);
        uint64_t rA1 = pair2(a[2],  a[3],  apw0.z, apw0.w, nsb, fb23, neg1);
        uint64_t rA2 = pair2(a[4],  a[5],  apw1.x, apw1.y, nsb, fb45, neg1);
        uint64_t rA3 = pair2(a[6],  a[7],  apw1.z, apw1.w, nsb, fb67, neg1);
        uint64_t rB0 = pair2(a[8],  a[9],  apw0.x, apw0.y, nsb, fb01, neg1);
        uint64_t rB1 = pair2(a[10], a[11], apw0.z, apw0.w, nsb, fb23, neg1);
        uint64_t rB2 = pair2(a[12], a[13], apw1.x, apw1.y, nsb, fb45, neg1);
        uint64_t rB3 = pair2(a[14], a[15], apw1.z, apw1.w, nsb, fb67, neg1);

        float* p = base + (size_t)sl * ROW_FLOATS;
        if (EL) { st4_el(p, rA0, rA1, rA2, rA3); st4_el(p + 8, rB0, rB1, rB2, rB3); }
        else    { st4_ef(p, rA0, rA1, rA2, rA3); st4_ef(p + 8, rB0, rB1, rB2, rB3); }
    }
}

__global__ __launch_bounds__(128)
void critigraph_kernel(const int* __restrict__ sta_loc,   // (T, TP)
                       const int* __restrict__ pos_loc,   // (T, S, TP)
                       const int* __restrict__ cnc_loc,   // (T, C, TP)
                       const float* __restrict__ eu_norm, // (T, S)
                       float* __restrict__ out)           // (T, S, C, TP)
{
    __shared__ __align__(16) uint32_t sm_apw[S_CHUNK][TPn]; // |pos| | sign<<31
    __shared__ __align__(16) float    sm_fb[S_CHUNK][TPn];  // (sum - d[p]) / 8
    __shared__ uint32_t sm_nsb[S_CHUNK];                    // bits(norm/128)

    const int t   = blockIdx.x;
    const int s0  = blockIdx.y * S_CHUNK;
    const int tid = threadIdx.x;

    // ---- phase A: per-(s,p) constants — all 128 threads, one (sl,p) each ----
    {
        const int sl = tid >> 3, p = tid & 7;
        const int s  = s0 + sl;
        const int pv = pos_loc[((size_t)t * Sn + s) * TPn + p];
        const uint32_t ap = (uint32_t)(pv < 0 ? -pv : pv);
        const int sv = sta_loc[t * TPn + p];
        const uint32_t as_ = (uint32_t)(sv < 0 ? -sv : sv);
        const float norm = eu_norm[t * Sn + s];

        const uint32_t x = as_ ^ ap;
        const int cl = __clz(x * 32768u + 32768u);
        float d = (float)(cl - 1) * 0.0625f * norm;
        if ((pv < 0) != (sv < 0)) d = -d;

        float sum = d;                                  // octet reduce over p
        sum += __shfl_xor_sync(0xffffffffu, sum, 1);
        sum += __shfl_xor_sync(0xffffffffu, sum, 2);
        sum += __shfl_xor_sync(0xffffffffu, sum, 4);

        sm_fb[sl][p]  = (sum - d) * 0.125f;
        sm_apw[sl][p] = ap | ((uint32_t)pv & 0x80000000u);
        if (p == 0) sm_nsb[sl] = __float_as_uint(norm * 0.0078125f);  // norm/128
    }

    // ---- register-resident cnc: thread owns connections 2*tid, 2*tid+1 (64B) ----
    const uint4* cnc_t = (const uint4*)(cnc_loc + (size_t)t * ROW_FLOATS);
    uint32_t a[16];
    #pragma unroll
    for (int j = 0; j < 4; j++) {
        uint4 q = cnc_t[4 * tid + j];
        a[4*j+0] = packsgn((int)q.x); a[4*j+1] = packsgn((int)q.y);
        a[4*j+2] = packsgn((int)q.z); a[4*j+3] = packsgn((int)q.w);
    }

    // distributed epilogue: c=256 for 16 s-lines, on threads tid%8==0
    uint32_t ae[8];
    const bool edo = (tid & 7) == 0;
    const int  esl = tid >> 3;             // 0..15
    if (edo) {
        uint4 e0 = cnc_t[512];
        uint4 e1 = cnc_t[513];
        ae[0] = packsgn((int)e0.x); ae[1] = packsgn((int)e0.y);
        ae[2] = packsgn((int)e0.z); ae[3] = packsgn((int)e0.w);
        ae[4] = packsgn((int)e1.x); ae[5] = packsgn((int)e1.y);
        ae[6] = packsgn((int)e1.z); ae[7] = packsgn((int)e1.w);
    }

    __syncthreads();

    float* base = out + ((size_t)t * Sn + s0) * ROW_FLOATS + (size_t)tid * 16;

    if (t < T_SPLIT) hot_loop<true >(a, sm_apw, sm_fb, sm_nsb, base);
    else             hot_loop<false>(a, sm_apw, sm_fb, sm_nsb, base);

    // ---- epilogue: connection c=256 for s-line esl ----
    if (edo) {
        const uint4 apw0 = *(const uint4*)&sm_apw[esl][0];
        const uint4 apw1 = *(const uint4*)&sm_apw[esl][4];
        uint64_t fb01, fb23, fb45, fb67;
        {
            uint32_t sa = (uint32_t)__cvta_generic_to_shared(&sm_fb[esl][0]);
            asm("ld.shared.v2.u64 {%0,%1}, [%2];" : "=l"(fb01), "=l"(fb23) : "r"(sa));
            asm("ld.shared.v2.u64 {%0,%1}, [%2];" : "=l"(fb45), "=l"(fb67) : "r"(sa + 16));
        }
        const uint32_t nsb = sm_nsb[esl];
        const uint64_t neg1 = NEG1X2;
        uint64_t r0 = pair2(ae[0], ae[1], apw0.x, apw0.y, nsb, fb01, neg1);
        uint64_t r1 = pair2(ae[2], ae[3], apw0.z, apw0.w, nsb, fb23, neg1);
        uint64_t r2 = pair2(ae[4], ae[5], apw1.x, apw1.y, nsb, fb45, neg1);
        uint64_t r3 = pair2(ae[6], ae[7], apw1.z, apw1.w, nsb, fb67, neg1);
        float* eptr = out + ((size_t)t * Sn + s0 + esl) * ROW_FLOATS + 2048;
        if (t < T_SPLIT) st4_el(eptr, r0, r1, r2, r3);
        else             st4_ef(eptr, r0, r1, r2, r3);
    }
}

extern "C" void kernel_launch(void* const* d_in, const int* in_sizes, int n_in,
                              void* d_out, int out_size)
{
    const int*   sta = (const int*)d_in[0];
    const int*   pos = (const int*)d_in[1];
    const int*   cnc = (const int*)d_in[2];
    const float* eu  = (const float*)d_in[3];
    dim3 grid(Tn, Sn / S_CHUNK);  // (128, 8) -> 1024 blocks of 128 threads
    critigraph_kernel<<<grid, 128>>>(sta, pos, cnc, eu, (float*)d_out);
}